// round 8
// baseline (speedup 1.0000x reference)
#include <cuda_runtime.h>

// Problem dims
#define NCC 4
#define BSZ 16
#define HH  64
#define WW  64
#define OCC 12
#define NTT 32
#define SSLICE (BSZ*HH*WW*OCC)   // 786432 floats per (BS,H,W,OC) slab

// Persistent device state (16B-aligned for float4 access)
// class_h lives in 5 rotating slabs; schedule below maps logical bank -> slab.
__device__ __align__(16) float g_slabs[5][SSLICE];
__device__ __align__(16) float g_class_c[NCC*SSLICE];
__device__ __align__(16) float g_genh[2][SSLICE];
__device__ __align__(16) float g_genc[SSLICE];

// Slab schedule, computed once per replay by zero_kernel thread 0:
//   g_rslab[t*4+c] = slab holding class_h[c] at the START of step t
//   g_wslab[t]     = slab that step t's cls writes h_new into
__device__ int g_rslab[NTT*NCC];
__device__ int g_wslab[NTT];

__device__ __forceinline__ float hsig(float x) {
    return fminf(fmaxf(x + 3.0f, 0.0f), 6.0f) * (1.0f/6.0f);
}

typedef unsigned long long ull;

__device__ __forceinline__ ull pack2(float x) {
    ull r;
    unsigned int xi = __float_as_uint(x);
    asm("mov.b64 %0, {%1, %1};" : "=l"(r) : "r"(xi));
    return r;
}
__device__ __forceinline__ void ffma2(ull& d, ull a, ull b) {
    asm("fma.rn.f32x2 %0, %1, %2, %0;" : "+l"(d) : "l"(a), "l"(b));
}
__device__ __forceinline__ float2 unpack2(ull v) {
    float2 r;
    asm("mov.b64 {%0, %1}, %2;" : "=f"(r.x), "=f"(r.y) : "l"(v));
    return r;
}

// --------------------------------------------------------------------------
// Software-pipelined 12-channel conv tap: weights for each channel are 48
// floats = 12 ulonglong2, split into two 24-oc halves (6 u2 each).
// While one half's 24-FFMA2 burst runs, the next half's LDS.128s are in
// flight -> weight-load latency fully hidden behind FMA work.
// One-past prefetch on the last icc overreads into the smem pad (harmless).
// xb: channel-major input, channel icc at xb[icc*660], row+1 at +66.
// --------------------------------------------------------------------------
__device__ __forceinline__ void conv12(const float* __restrict__ sWk,
                                       const float* __restrict__ xb,
                                       ull* __restrict__ acc0,
                                       ull* __restrict__ acc1)
{
    const ulonglong2* wp = (const ulonglong2*)sWk;   // 12 u2 per channel
    ulonglong2 h0[6];
    #pragma unroll
    for (int j = 0; j < 6; ++j) h0[j] = wp[j];
    float x0 = xb[0], x1 = xb[66];

    #pragma unroll 2
    for (int icc = 0; icc < 12; ++icc) {
        ulonglong2 h1[6];
        #pragma unroll
        for (int j = 0; j < 6; ++j) h1[j] = wp[icc*12 + 6 + j];
        ull xp0 = pack2(x0), xp1 = pack2(x1);
        #pragma unroll
        for (int p = 0; p < 6; ++p) {
            ffma2(acc0[2*p],   xp0, h0[p].x);
            ffma2(acc0[2*p+1], xp0, h0[p].y);
            ffma2(acc1[2*p],   xp1, h0[p].x);
            ffma2(acc1[2*p+1], xp1, h0[p].y);
        }
        // prefetch next channel's first half + x (overreads pad at icc=11)
        #pragma unroll
        for (int j = 0; j < 6; ++j) h0[j] = wp[(icc+1)*12 + j];
        x0 = xb[(icc+1)*660];
        x1 = xb[(icc+1)*660 + 66];
        #pragma unroll
        for (int p = 0; p < 6; ++p) {
            ffma2(acc0[12+2*p],   xp0, h1[p].x);
            ffma2(acc0[12+2*p+1], xp0, h1[p].y);
            ffma2(acc1[12+2*p],   xp1, h1[p].x);
            ffma2(acc1[12+2*p+1], xp1, h1[p].y);
        }
    }
}

// --------------------------------------------------------------------------
__global__ void zero_kernel(float* __restrict__ out, const int* __restrict__ cids)
{
    const int tid    = blockIdx.x * blockDim.x + threadIdx.x;
    const int stride = gridDim.x * blockDim.x;
    for (int i = tid; i < 5*SSLICE; i += stride)
        (&g_slabs[0][0])[i] = 0.0f;
    for (int i = tid; i < NCC*SSLICE; i += stride)
        g_class_c[i] = 0.0f;
    for (int i = tid; i < SSLICE; i += stride) {
        g_genh[0][i] = 0.0f;
        g_genc[i]    = 0.0f;
        out[i]       = 0.0f;
    }
    if (tid == 0) {
        int slab[NCC] = {0, 1, 2, 3};
        int spare = 4;
        for (int t = 0; t < NTT; ++t) {
            int cid = cids[t];
            #pragma unroll
            for (int c = 0; c < NCC; ++c) g_rslab[t*4 + c] = slab[c];
            g_wslab[t] = spare;
            int old = slab[cid];
            slab[cid] = spare;
            spare = old;
        }
    }
}

// ==========================================================================
// General cell: 60 in-ch = 5 chunks of 12 (4 class banks flat view + gen_h),
// 48 gate-ch out. grid (8,16)=(row-tile,batch), block 256 = 64 cols x 4
// row-groups; each thread 2 rows x 48 oc as 24 f32x2 accumulators per row.
// Input tile is channel-major [12][660].
// ==========================================================================
#define A_SW   (9*60*48)            // 25920 floats
#define A_SIN  (12*660)             // 7920 floats, [icc][10 rows x 66 cols]
#define A_PAD  720                  // absorbs one-past channel prefetch
#define A_SMEM_BYTES ((A_SW + A_SIN + 48 + A_PAD)*4)

__global__ __launch_bounds__(256, 1)
void gen_cell_kernel(const float* __restrict__ Wx, const float* __restrict__ Wh,
                     const float* __restrict__ bias, int t, int par)
{
    extern __shared__ float smem[];
    float* sW  = smem;                 // [9][60][48]
    float* sIn = smem + A_SW;          // [12][660]
    float* sB  = smem + A_SW + A_SIN;  // [48] bias (+pad after)

    const int tid = threadIdx.x;
    const int tx  = tid & 63;
    const int rg  = tid >> 6;
    const int b   = blockIdx.y;
    const int y0  = blockIdx.x * 8;
    const float* bankp = g_slabs[g_rslab[t*4 + (b >> 2)]];

    const float* genh_in  = g_genh[par];
    float*       genh_out = g_genh[par ^ 1];

    // Stage weights: per tap k, Wx block (48x48) then Wh block (12x48)
    for (int k = 0; k < 9; ++k) {
        const float4* sx = (const float4*)(Wx + k*48*48);
        float4*       dx = (float4*)(sW + (k*60)*48);
        for (int e = tid; e < 576; e += 256) dx[e] = sx[e];
        const float4* sh = (const float4*)(Wh + k*12*48);
        float4*       dh = (float4*)(sW + (k*60 + 48)*48);
        if (tid < 144) dh[tid] = sh[tid];
    }
    if (tid < 12) ((float4*)sB)[tid] = ((const float4*)bias)[tid];

    ull acc0[24], acc1[24];
    #pragma unroll
    for (int p = 0; p < 24; ++p) { acc0[p] = 0ull; acc1[p] = 0ull; }

    #pragma unroll 1
    for (int ch = 0; ch < 5; ++ch) {
        __syncthreads();
        // Stage 12-ch chunk: gmem float4 loads, transpose to [icc][660]
        #pragma unroll 1
        for (int e = tid; e < 1980; e += 256) {
            int px = e / 3;
            int q  = e - px*3;
            int yy = px / 66;
            int xx = px - yy*66;
            int gy = y0 + yy - 1;
            int gx = xx - 1;
            float4 v = make_float4(0.f, 0.f, 0.f, 0.f);
            if ((unsigned)gy < 64u && (unsigned)gx < 64u) {
                int pidx = (b*64 + gy)*64 + gx;
                const float* src = (ch < 4)
                    ? bankp   + (size_t)(pidx & 16383)*48 + ch*12
                    : genh_in + (size_t)pidx*12;
                v = *(const float4*)(src + q*4);
            }
            sIn[(q*4 + 0)*660 + px] = v.x;
            sIn[(q*4 + 1)*660 + px] = v.y;
            sIn[(q*4 + 2)*660 + px] = v.z;
            sIn[(q*4 + 3)*660 + px] = v.w;
        }
        __syncthreads();

        #pragma unroll 1
        for (int k = 0; k < 9; ++k) {
            const int ky = k / 3;
            const int kx = k - ky*3;
            conv12(sW + (k*60 + ch*12)*48,
                   sIn + (rg*2 + ky)*66 + tx + kx,
                   acc0, acc1);
        }
    }

    // Local LSTM epilogue, vectorized c/h traffic
    #pragma unroll
    for (int r = 0; r < 2; ++r) {
        ull* accr = r ? acc1 : acc0;
        float z[48];
        #pragma unroll
        for (int p = 0; p < 24; ++p) {
            float2 v = unpack2(accr[p]);
            z[2*p] = v.x; z[2*p+1] = v.y;
        }
        const int gy  = y0 + rg*2 + r;
        const int idx = ((b*64 + gy)*64 + tx)*12;
        float4 c4[3], h4[3];
        #pragma unroll
        for (int q = 0; q < 3; ++q) c4[q] = ((const float4*)(g_genc + idx))[q];
        float* cf = (float*)c4;
        float* hf = (float*)h4;
        #pragma unroll
        for (int j = 0; j < 12; ++j) {
            float zi = z[j]      + sB[j];
            float zf = z[12 + j] + sB[12 + j];
            float zg = z[24 + j] + sB[24 + j];
            float zo = z[36 + j] + sB[36 + j];
            float fi = hsig(zi), ff = hsig(zf), fo = hsig(zo);
            float cn = ff * cf[j] + fi * tanhf(zg);
            cf[j] = cn;
            hf[j] = fo * tanhf(cn);
        }
        #pragma unroll
        for (int q = 0; q < 3; ++q) {
            ((float4*)(g_genc + idx))[q]   = c4[q];
            ((float4*)(genh_out + idx))[q] = h4[q];
        }
    }
}

// ==========================================================================
// Class cell: 36 in-ch = 3 chunks of 12 (frame, fresh gen_h, class_h[cid]).
// Reads class_h[cid] from slab rslab[t][cid]; writes h_new into slab
// wslab[t] (no copy); accumulates the output sum directly.
// ==========================================================================
#define B_SW   (9*36*48)            // 15552 floats
#define B_SIN  (12*660)
#define B_PAD  720
#define B_SMEM_BYTES ((B_SW + B_SIN + 48 + B_PAD)*4)

__global__ __launch_bounds__(256, 1)
void cls_cell_kernel(const float* __restrict__ x, const int* __restrict__ class_ids,
                     const float* __restrict__ Wx, const float* __restrict__ Wh,
                     const float* __restrict__ bias, int t, int par,
                     float* __restrict__ out)
{
    extern __shared__ float smem[];
    float* sW  = smem;
    float* sIn = smem + B_SW;
    float* sB  = smem + B_SW + B_SIN;

    const int tid = threadIdx.x;
    const int tx  = tid & 63;
    const int rg  = tid >> 6;
    const int b   = blockIdx.y;
    const int y0  = blockIdx.x * 8;
    const int cid = __ldg(class_ids + t);

    const float* genh_new = g_genh[par ^ 1];
    const float* chh      = g_slabs[g_rslab[t*4 + cid]];
    float*       hnew     = g_slabs[g_wslab[t]];
    const float* frame    = x + (size_t)(b*NTT + t)*4096*12;

    for (int k = 0; k < 9; ++k) {
        const float4* sx = (const float4*)(Wx + k*24*48);
        float4*       dx = (float4*)(sW + (k*36)*48);
        for (int e = tid; e < 288; e += 256) dx[e] = sx[e];
        const float4* sh = (const float4*)(Wh + k*12*48);
        float4*       dh = (float4*)(sW + (k*36 + 24)*48);
        if (tid < 144) dh[tid] = sh[tid];
    }
    if (tid < 12) ((float4*)sB)[tid] = ((const float4*)bias)[tid];

    ull acc0[24], acc1[24];
    #pragma unroll
    for (int p = 0; p < 24; ++p) { acc0[p] = 0ull; acc1[p] = 0ull; }

    #pragma unroll 1
    for (int ch = 0; ch < 3; ++ch) {
        __syncthreads();
        #pragma unroll 1
        for (int e = tid; e < 1980; e += 256) {
            int px = e / 3;
            int q  = e - px*3;
            int yy = px / 66;
            int xx = px - yy*66;
            int gy = y0 + yy - 1;
            int gx = xx - 1;
            float4 v = make_float4(0.f, 0.f, 0.f, 0.f);
            if ((unsigned)gy < 64u && (unsigned)gx < 64u) {
                int lpix = gy*64 + gx;
                int pidx = b*4096 + lpix;
                const float* src = (ch == 0) ? frame + (size_t)lpix*12
                                 : (ch == 1) ? genh_new + (size_t)pidx*12
                                             : chh + (size_t)pidx*12;
                v = *(const float4*)(src + q*4);
            }
            sIn[(q*4 + 0)*660 + px] = v.x;
            sIn[(q*4 + 1)*660 + px] = v.y;
            sIn[(q*4 + 2)*660 + px] = v.z;
            sIn[(q*4 + 3)*660 + px] = v.w;
        }
        __syncthreads();

        #pragma unroll 1
        for (int k = 0; k < 9; ++k) {
            const int ky = k / 3;
            const int kx = k - ky*3;
            conv12(sW + (k*36 + ch*12)*48,
                   sIn + (rg*2 + ky)*66 + tx + kx,
                   acc0, acc1);
        }
    }

    float* chc = g_class_c + (size_t)cid * SSLICE;

    #pragma unroll
    for (int r = 0; r < 2; ++r) {
        ull* accr = r ? acc1 : acc0;
        float z[48];
        #pragma unroll
        for (int p = 0; p < 24; ++p) {
            float2 v = unpack2(accr[p]);
            z[2*p] = v.x; z[2*p+1] = v.y;
        }
        const int gy  = y0 + rg*2 + r;
        const int idx = ((b*64 + gy)*64 + tx)*12;
        float4 c4[3], h4[3], o4[3];
        #pragma unroll
        for (int q = 0; q < 3; ++q) {
            c4[q] = ((const float4*)(chc + idx))[q];
            o4[q] = ((const float4*)(out + idx))[q];
        }
        float* cf = (float*)c4;
        float* hf = (float*)h4;
        float* of = (float*)o4;
        #pragma unroll
        for (int j = 0; j < 12; ++j) {
            float zi = z[j]      + sB[j];
            float zf = z[12 + j] + sB[12 + j];
            float zg = z[24 + j] + sB[24 + j];
            float zo = z[36 + j] + sB[36 + j];
            float fi = hsig(zi), ff = hsig(zf), fo = hsig(zo);
            float cn = ff * cf[j] + fi * tanhf(zg);
            float hn = fo * tanhf(cn);
            cf[j] = cn;
            hf[j] = hn;
            of[j] += hn;
        }
        #pragma unroll
        for (int q = 0; q < 3; ++q) {
            ((float4*)(chc + idx))[q]  = c4[q];
            ((float4*)(hnew + idx))[q] = h4[q];
            ((float4*)(out + idx))[q]  = o4[q];
        }
    }
}

// --------------------------------------------------------------------------
extern "C" void kernel_launch(void* const* d_in, const int* in_sizes, int n_in,
                              void* d_out, int out_size)
{
    const float* x    = (const float*)d_in[0];
    const int*   cids = (const int*)d_in[1];
    const float* Wxg  = (const float*)d_in[2];
    const float* Whg  = (const float*)d_in[3];
    const float* bg   = (const float*)d_in[4];
    const float* Wxc  = (const float*)d_in[5];
    const float* Whc  = (const float*)d_in[6];
    const float* bc   = (const float*)d_in[7];
    float* out = (float*)d_out;

    cudaFuncSetAttribute(gen_cell_kernel, cudaFuncAttributeMaxDynamicSharedMemorySize, A_SMEM_BYTES);
    cudaFuncSetAttribute(cls_cell_kernel, cudaFuncAttributeMaxDynamicSharedMemorySize, B_SMEM_BYTES);

    zero_kernel<<<1024, 256>>>(out, cids);

    for (int t = 0; t < NTT; ++t) {
        const int par = t & 1;
        gen_cell_kernel<<<dim3(8, 16), 256, A_SMEM_BYTES>>>(Wxg, Whg, bg, t, par);
        cls_cell_kernel<<<dim3(8, 16), 256, B_SMEM_BYTES>>>(x, cids, Wxc, Whc, bc, t, par, out);
    }
}

// round 9
// speedup vs baseline: 1.1683x; 1.1683x over previous
#include <cuda_runtime.h>

// Problem dims
#define NCC 4
#define BSZ 16
#define HH  64
#define WW  64
#define OCC 12
#define NTT 32
#define SSLICE (BSZ*HH*WW*OCC)   // 786432 floats per (BS,H,W,OC) slab

// Persistent device state (16B-aligned for float4 access)
// class_h lives in 5 rotating slabs; schedule below maps logical bank -> slab.
__device__ __align__(16) float g_slabs[5][SSLICE];
__device__ __align__(16) float g_class_c[NCC*SSLICE];
__device__ __align__(16) float g_genh[2][SSLICE];
__device__ __align__(16) float g_genc[SSLICE];

// Slab schedule, computed once per replay by zero_kernel thread 0:
//   g_rslab[t*4+c] = slab holding class_h[c] at the START of step t
//   g_wslab[t]     = slab that step t's cls writes h_new into
__device__ int g_rslab[NTT*NCC];
__device__ int g_wslab[NTT];

__device__ __forceinline__ float hsig(float x) {
    return fminf(fmaxf(x + 3.0f, 0.0f), 6.0f) * (1.0f/6.0f);
}

typedef unsigned long long ull;

__device__ __forceinline__ ull pack2(float x) {
    ull r;
    unsigned int xi = __float_as_uint(x);
    asm("mov.b64 %0, {%1, %1};" : "=l"(r) : "r"(xi));
    return r;
}
__device__ __forceinline__ void ffma2(ull& d, ull a, ull b) {
    asm("fma.rn.f32x2 %0, %1, %2, %0;" : "+l"(d) : "l"(a), "l"(b));
}
__device__ __forceinline__ float2 unpack2(ull v) {
    float2 r;
    asm("mov.b64 {%0, %1}, %2;" : "=f"(r.x), "=f"(r.y) : "l"(v));
    return r;
}

// --------------------------------------------------------------------------
// 12-channel conv tap, 24-oc half per thread.
// Weights in smem at [ic][half][24] granularity: per channel stride 48
// floats (12 u2), this thread's half contiguous (6 u2, 16B aligned).
// xb channel-major: channel icc at xb[icc*660], next row +66.
// --------------------------------------------------------------------------
__device__ __forceinline__ void conv12h(const float* __restrict__ sWk,
                                        const float* __restrict__ xb,
                                        ull* __restrict__ acc0,
                                        ull* __restrict__ acc1)
{
    const ulonglong2* wp = (const ulonglong2*)sWk;
    #pragma unroll 2
    for (int icc = 0; icc < 12; ++icc) {
        ull xp0 = pack2(xb[icc*660]);
        ull xp1 = pack2(xb[icc*660 + 66]);
        const ulonglong2* w = wp + icc*12;   // 48-float per-channel stride
        #pragma unroll
        for (int p = 0; p < 6; ++p) {
            ulonglong2 ww = w[p];
            ffma2(acc0[2*p],   xp0, ww.x);
            ffma2(acc0[2*p+1], xp0, ww.y);
            ffma2(acc1[2*p],   xp1, ww.x);
            ffma2(acc1[2*p+1], xp1, ww.y);
        }
    }
}

// --------------------------------------------------------------------------
__global__ void zero_kernel(float* __restrict__ out, const int* __restrict__ cids)
{
    const int tid    = blockIdx.x * blockDim.x + threadIdx.x;
    const int stride = gridDim.x * blockDim.x;
    for (int i = tid; i < 5*SSLICE; i += stride)
        (&g_slabs[0][0])[i] = 0.0f;
    for (int i = tid; i < NCC*SSLICE; i += stride)
        g_class_c[i] = 0.0f;
    for (int i = tid; i < SSLICE; i += stride) {
        g_genh[0][i] = 0.0f;
        g_genc[i]    = 0.0f;
        out[i]       = 0.0f;
    }
    if (tid == 0) {
        int slab[NCC] = {0, 1, 2, 3};
        int spare = 4;
        for (int t = 0; t < NTT; ++t) {
            int cid = cids[t];
            #pragma unroll
            for (int c = 0; c < NCC; ++c) g_rslab[t*4 + c] = slab[c];
            g_wslab[t] = spare;
            int old = slab[cid];
            slab[cid] = spare;
            spare = old;
        }
    }
}

// ==========================================================================
// General cell: 60 in-ch, 48 gate-ch out. grid (8,16)=(row-tile,batch),
// block 512 = 64 cols x 4 rowgroups x 2 oc-halves; each thread 2 rows x
// 24 oc (channels h*6..h*6+5 of all 4 gates) -> local LSTM epilogue.
// Smem weights reordered to [k][ic][half][gate][6].
// ==========================================================================
#define A_SW   (9*60*48)            // 25920 floats
#define A_SIN  (12*660)             // 7920 floats, [icc][10 rows x 66 cols]
#define A_SMEM_BYTES ((A_SW + A_SIN + 48)*4)

__global__ __launch_bounds__(512, 1)
void gen_cell_kernel(const float* __restrict__ Wx, const float* __restrict__ Wh,
                     const float* __restrict__ bias, int t, int par)
{
    extern __shared__ float smem[];
    float* sW  = smem;                 // [9][60][2][24]
    float* sIn = smem + A_SW;          // [12][660]
    float* sB  = smem + A_SW + A_SIN;  // [48] bias

    const int tid = threadIdx.x;
    const int tx  = tid & 63;
    const int rg  = (tid >> 6) & 3;
    const int hh  = tid >> 8;          // oc half: channels hh*6..hh*6+5
    const int b   = blockIdx.y;
    const int y0  = blockIdx.x * 8;
    const float* bankp = g_slabs[g_rslab[t*4 + (b >> 2)]];

    const float* genh_in  = g_genh[par];
    float*       genh_out = g_genh[par ^ 1];

    // Stage weights reordered: dst[k][ic][h][gate][j0..5], float2 granular.
    // src oc = gate*12 + h*6 + j2*2
    for (int e = tid; e < 9*60*24; e += 512) {
        int j2   = e % 3;
        int gate = (e/3) % 4;
        int h    = (e/12) % 2;
        int ic   = (e/24) % 60;
        int k    = e / 1440;
        int oc   = gate*12 + h*6 + j2*2;
        float2 v = (ic < 48)
            ? *(const float2*)(Wx + (k*48 + ic)*48 + oc)
            : *(const float2*)(Wh + (k*12 + (ic - 48))*48 + oc);
        ((float2*)sW)[((k*60 + ic)*2 + h)*12 + gate*3 + j2] = v;
    }
    if (tid < 12) ((float4*)sB)[tid] = ((const float4*)bias)[tid];

    ull acc0[12], acc1[12];
    #pragma unroll
    for (int p = 0; p < 12; ++p) { acc0[p] = 0ull; acc1[p] = 0ull; }

    #pragma unroll 1
    for (int ch = 0; ch < 5; ++ch) {
        __syncthreads();
        // Stage 12-ch chunk: gmem float4 loads, transpose to [icc][660]
        #pragma unroll 1
        for (int e = tid; e < 1980; e += 512) {
            int px = e / 3;
            int q  = e - px*3;
            int yy = px / 66;
            int xx = px - yy*66;
            int gy = y0 + yy - 1;
            int gx = xx - 1;
            float4 v = make_float4(0.f, 0.f, 0.f, 0.f);
            if ((unsigned)gy < 64u && (unsigned)gx < 64u) {
                int pidx = (b*64 + gy)*64 + gx;
                const float* src = (ch < 4)
                    ? bankp   + (size_t)(pidx & 16383)*48 + ch*12
                    : genh_in + (size_t)pidx*12;
                v = *(const float4*)(src + q*4);
            }
            sIn[(q*4 + 0)*660 + px] = v.x;
            sIn[(q*4 + 1)*660 + px] = v.y;
            sIn[(q*4 + 2)*660 + px] = v.z;
            sIn[(q*4 + 3)*660 + px] = v.w;
        }
        __syncthreads();

        #pragma unroll 1
        for (int k = 0; k < 9; ++k) {
            const int ky = k / 3;
            const int kx = k - ky*3;
            conv12h(sW + ((k*60 + ch*12)*2 + hh)*24,
                    sIn + (rg*2 + ky)*66 + tx + kx,
                    acc0, acc1);
        }
    }

    // Local LSTM epilogue for channels hh*6..hh*6+5 (all 4 gates local)
    #pragma unroll
    for (int r = 0; r < 2; ++r) {
        ull* accr = r ? acc1 : acc0;
        float z[24];   // [i0..5 | f0..5 | g0..5 | o0..5]
        #pragma unroll
        for (int p = 0; p < 12; ++p) {
            float2 v = unpack2(accr[p]);
            z[2*p] = v.x; z[2*p+1] = v.y;
        }
        const int gy  = y0 + rg*2 + r;
        const int idx = ((b*64 + gy)*64 + tx)*12 + hh*6;
        float2 c2[3], h2[3];
        #pragma unroll
        for (int q = 0; q < 3; ++q) c2[q] = ((const float2*)(g_genc + idx))[q];
        float* cf = (float*)c2;
        float* hf = (float*)h2;
        #pragma unroll
        for (int j = 0; j < 6; ++j) {
            float zi = z[j]      + sB[hh*6 + j];
            float zf = z[6 + j]  + sB[12 + hh*6 + j];
            float zg = z[12 + j] + sB[24 + hh*6 + j];
            float zo = z[18 + j] + sB[36 + hh*6 + j];
            float fi = hsig(zi), ff = hsig(zf), fo = hsig(zo);
            float cn = ff * cf[j] + fi * tanhf(zg);
            cf[j] = cn;
            hf[j] = fo * tanhf(cn);
        }
        #pragma unroll
        for (int q = 0; q < 3; ++q) {
            ((float2*)(g_genc + idx))[q]   = c2[q];
            ((float2*)(genh_out + idx))[q] = h2[q];
        }
    }
}

// ==========================================================================
// Class cell: 36 in-ch = 3 chunks of 12 (frame, fresh gen_h, class_h[cid]).
// Same 512-thread oc-half layout. Writes h_new into slab wslab[t] and
// accumulates the output sum directly.
// ==========================================================================
#define B_SW   (9*36*48)            // 15552 floats
#define B_SIN  (12*660)
#define B_SMEM_BYTES ((B_SW + B_SIN + 48)*4)

__global__ __launch_bounds__(512, 1)
void cls_cell_kernel(const float* __restrict__ x, const int* __restrict__ class_ids,
                     const float* __restrict__ Wx, const float* __restrict__ Wh,
                     const float* __restrict__ bias, int t, int par,
                     float* __restrict__ out)
{
    extern __shared__ float smem[];
    float* sW  = smem;                 // [9][36][2][24]
    float* sIn = smem + B_SW;
    float* sB  = smem + B_SW + B_SIN;

    const int tid = threadIdx.x;
    const int tx  = tid & 63;
    const int rg  = (tid >> 6) & 3;
    const int hh  = tid >> 8;
    const int b   = blockIdx.y;
    const int y0  = blockIdx.x * 8;
    const int cid = __ldg(class_ids + t);

    const float* genh_new = g_genh[par ^ 1];
    const float* chh      = g_slabs[g_rslab[t*4 + cid]];
    float*       hnew     = g_slabs[g_wslab[t]];
    const float* frame    = x + (size_t)(b*NTT + t)*4096*12;

    for (int e = tid; e < 9*36*24; e += 512) {
        int j2   = e % 3;
        int gate = (e/3) % 4;
        int h    = (e/12) % 2;
        int ic   = (e/24) % 36;
        int k    = e / 864;
        int oc   = gate*12 + h*6 + j2*2;
        float2 v = (ic < 24)
            ? *(const float2*)(Wx + (k*24 + ic)*48 + oc)
            : *(const float2*)(Wh + (k*12 + (ic - 24))*48 + oc);
        ((float2*)sW)[((k*36 + ic)*2 + h)*12 + gate*3 + j2] = v;
    }
    if (tid < 12) ((float4*)sB)[tid] = ((const float4*)bias)[tid];

    ull acc0[12], acc1[12];
    #pragma unroll
    for (int p = 0; p < 12; ++p) { acc0[p] = 0ull; acc1[p] = 0ull; }

    #pragma unroll 1
    for (int ch = 0; ch < 3; ++ch) {
        __syncthreads();
        #pragma unroll 1
        for (int e = tid; e < 1980; e += 512) {
            int px = e / 3;
            int q  = e - px*3;
            int yy = px / 66;
            int xx = px - yy*66;
            int gy = y0 + yy - 1;
            int gx = xx - 1;
            float4 v = make_float4(0.f, 0.f, 0.f, 0.f);
            if ((unsigned)gy < 64u && (unsigned)gx < 64u) {
                int lpix = gy*64 + gx;
                int pidx = b*4096 + lpix;
                const float* src = (ch == 0) ? frame + (size_t)lpix*12
                                 : (ch == 1) ? genh_new + (size_t)pidx*12
                                             : chh + (size_t)pidx*12;
                v = *(const float4*)(src + q*4);
            }
            sIn[(q*4 + 0)*660 + px] = v.x;
            sIn[(q*4 + 1)*660 + px] = v.y;
            sIn[(q*4 + 2)*660 + px] = v.z;
            sIn[(q*4 + 3)*660 + px] = v.w;
        }
        __syncthreads();

        #pragma unroll 1
        for (int k = 0; k < 9; ++k) {
            const int ky = k / 3;
            const int kx = k - ky*3;
            conv12h(sW + ((k*36 + ch*12)*2 + hh)*24,
                    sIn + (rg*2 + ky)*66 + tx + kx,
                    acc0, acc1);
        }
    }

    float* chc = g_class_c + (size_t)cid * SSLICE;

    #pragma unroll
    for (int r = 0; r < 2; ++r) {
        ull* accr = r ? acc1 : acc0;
        float z[24];
        #pragma unroll
        for (int p = 0; p < 12; ++p) {
            float2 v = unpack2(accr[p]);
            z[2*p] = v.x; z[2*p+1] = v.y;
        }
        const int gy  = y0 + rg*2 + r;
        const int idx = ((b*64 + gy)*64 + tx)*12 + hh*6;
        float2 c2[3], h2[3], o2[3];
        #pragma unroll
        for (int q = 0; q < 3; ++q) {
            c2[q] = ((const float2*)(chc + idx))[q];
            o2[q] = ((const float2*)(out + idx))[q];
        }
        float* cf = (float*)c2;
        float* hf = (float*)h2;
        float* of = (float*)o2;
        #pragma unroll
        for (int j = 0; j < 6; ++j) {
            float zi = z[j]      + sB[hh*6 + j];
            float zf = z[6 + j]  + sB[12 + hh*6 + j];
            float zg = z[12 + j] + sB[24 + hh*6 + j];
            float zo = z[18 + j] + sB[36 + hh*6 + j];
            float fi = hsig(zi), ff = hsig(zf), fo = hsig(zo);
            float cn = ff * cf[j] + fi * tanhf(zg);
            float hn = fo * tanhf(cn);
            cf[j] = cn;
            hf[j] = hn;
            of[j] += hn;
        }
        #pragma unroll
        for (int q = 0; q < 3; ++q) {
            ((float2*)(chc + idx))[q]  = c2[q];
            ((float2*)(hnew + idx))[q] = h2[q];
            ((float2*)(out + idx))[q]  = o2[q];
        }
    }
}

// --------------------------------------------------------------------------
extern "C" void kernel_launch(void* const* d_in, const int* in_sizes, int n_in,
                              void* d_out, int out_size)
{
    const float* x    = (const float*)d_in[0];
    const int*   cids = (const int*)d_in[1];
    const float* Wxg  = (const float*)d_in[2];
    const float* Whg  = (const float*)d_in[3];
    const float* bg   = (const float*)d_in[4];
    const float* Wxc  = (const float*)d_in[5];
    const float* Whc  = (const float*)d_in[6];
    const float* bc   = (const float*)d_in[7];
    float* out = (float*)d_out;

    cudaFuncSetAttribute(gen_cell_kernel, cudaFuncAttributeMaxDynamicSharedMemorySize, A_SMEM_BYTES);
    cudaFuncSetAttribute(cls_cell_kernel, cudaFuncAttributeMaxDynamicSharedMemorySize, B_SMEM_BYTES);

    zero_kernel<<<1024, 256>>>(out, cids);

    for (int t = 0; t < NTT; ++t) {
        const int par = t & 1;
        gen_cell_kernel<<<dim3(8, 16), 512, A_SMEM_BYTES>>>(Wxg, Whg, bg, t, par);
        cls_cell_kernel<<<dim3(8, 16), 512, B_SMEM_BYTES>>>(x, cids, Wxc, Whc, bc, t, par, out);
    }
}

// round 11
// speedup vs baseline: 1.2211x; 1.0453x over previous
#include <cuda_runtime.h>

// Problem dims
#define NCC 4
#define BSZ 16
#define HH  64
#define WW  64
#define OCC 12
#define NTT 32
#define SSLICE (BSZ*HH*WW*OCC)   // 786432 floats per (BS,H,W,OC) slab

// Persistent device state (16B-aligned for float4 access)
__device__ __align__(16) float g_slabs[5][SSLICE];
__device__ __align__(16) float g_class_c[NCC*SSLICE];
__device__ __align__(16) float g_genh[2][SSLICE];
__device__ __align__(16) float g_genc[SSLICE];

// Reordered weights, produced once per replay by reorder_kernel:
// layout [k][ic][third][gate][4] (floats); third th owns oc channels
// gate*12 + th*4 .. +3 for every gate.
__device__ __align__(16) float g_wg[9*60*48];
__device__ __align__(16) float g_wc[9*36*48];

// Slab schedule: g_rslab[t*4+c] = slab holding class_h[c] at start of step t;
// g_wslab[t] = slab step t's cls writes h_new into.
__device__ int g_rslab[NTT*NCC];
__device__ int g_wslab[NTT];

__device__ __forceinline__ float hsig(float x) {
    return fminf(fmaxf(x + 3.0f, 0.0f), 6.0f) * (1.0f/6.0f);
}

typedef unsigned long long ull;

__device__ __forceinline__ ull pack2(float x) {
    ull r;
    unsigned int xi = __float_as_uint(x);
    asm("mov.b64 %0, {%1, %1};" : "=l"(r) : "r"(xi));
    return r;
}
__device__ __forceinline__ void ffma2(ull& d, ull a, ull b) {
    asm("fma.rn.f32x2 %0, %1, %2, %0;" : "+l"(d) : "l"(a), "l"(b));
}
__device__ __forceinline__ float2 unpack2(ull v) {
    float2 r;
    asm("mov.b64 {%0, %1}, %2;" : "=f"(r.x), "=f"(r.y) : "l"(v));
    return r;
}

// --------------------------------------------------------------------------
// 12-channel conv tap, 16-oc third per thread. Weights: per channel this
// thread's 16 floats are contiguous (4 u2); channel stride 48 floats = 12 u2
// (one ulonglong2 = 16 bytes = 4 floats).
// xb channel-major: channel icc at xb[icc*660], next row +66.
// --------------------------------------------------------------------------
__device__ __forceinline__ void conv12t(const float* __restrict__ sWk,
                                        const float* __restrict__ xb,
                                        ull* __restrict__ acc0,
                                        ull* __restrict__ acc1)
{
    const ulonglong2* wp = (const ulonglong2*)sWk;
    #pragma unroll 2
    for (int icc = 0; icc < 12; ++icc) {
        ull xp0 = pack2(xb[icc*660]);
        ull xp1 = pack2(xb[icc*660 + 66]);
        const ulonglong2* w = wp + icc*12;   // 48-float channel stride
        #pragma unroll
        for (int p = 0; p < 4; ++p) {
            ulonglong2 ww = w[p];
            ffma2(acc0[2*p],   xp0, ww.x);
            ffma2(acc0[2*p+1], xp0, ww.y);
            ffma2(acc1[2*p],   xp1, ww.x);
            ffma2(acc1[2*p+1], xp1, ww.y);
        }
    }
}

// --------------------------------------------------------------------------
__global__ void zero_kernel(float* __restrict__ out, const int* __restrict__ cids)
{
    const int tid    = blockIdx.x * blockDim.x + threadIdx.x;
    const int stride = gridDim.x * blockDim.x;
    for (int i = tid; i < 5*SSLICE; i += stride)
        (&g_slabs[0][0])[i] = 0.0f;
    for (int i = tid; i < NCC*SSLICE; i += stride)
        g_class_c[i] = 0.0f;
    for (int i = tid; i < SSLICE; i += stride) {
        g_genh[0][i] = 0.0f;
        g_genc[i]    = 0.0f;
        out[i]       = 0.0f;
    }
    if (tid == 0) {
        int slab[NCC] = {0, 1, 2, 3};
        int spare = 4;
        for (int t = 0; t < NTT; ++t) {
            int cid = cids[t];
            #pragma unroll
            for (int c = 0; c < NCC; ++c) g_rslab[t*4 + c] = slab[c];
            g_wslab[t] = spare;
            int old = slab[cid];
            slab[cid] = spare;
            spare = old;
        }
    }
}

// --------------------------------------------------------------------------
// One-time weight reorder into [k][ic][third][gate][4] layout.
// src oc = gate*12 + th*4 + j; float4-granular on both sides.
// --------------------------------------------------------------------------
__global__ void reorder_kernel(const float* __restrict__ Wxg, const float* __restrict__ Whg,
                               const float* __restrict__ Wxc, const float* __restrict__ Whc)
{
    const int tid    = blockIdx.x * blockDim.x + threadIdx.x;
    const int stride = gridDim.x * blockDim.x;
    const float4* wx4 = (const float4*)Wxg;
    const float4* wh4 = (const float4*)Whg;
    for (int e = tid; e < 9*60*12; e += stride) {
        int th   = e % 3;
        int gate = (e/3) & 3;
        int ic   = (e/12) % 60;
        int k    = e / 720;
        float4 v = (ic < 48) ? wx4[(k*48 + ic)*12 + gate*3 + th]
                             : wh4[(k*12 + (ic - 48))*12 + gate*3 + th];
        ((float4*)g_wg)[((k*60 + ic)*3 + th)*4 + gate] = v;
    }
    const float4* cx4 = (const float4*)Wxc;
    const float4* ch4 = (const float4*)Whc;
    for (int e = tid; e < 9*36*12; e += stride) {
        int th   = e % 3;
        int gate = (e/3) & 3;
        int ic   = (e/12) % 36;
        int k    = e / 432;
        float4 v = (ic < 24) ? cx4[(k*24 + ic)*12 + gate*3 + th]
                             : ch4[(k*12 + (ic - 24))*12 + gate*3 + th];
        ((float4*)g_wc)[((k*36 + ic)*3 + th)*4 + gate] = v;
    }
}

// --------------------------------------------------------------------------
__device__ __forceinline__ float4 ldsrc_gen(const float* __restrict__ bankp,
                                            const float* __restrict__ genh_in,
                                            int ch, int pidx, int q, bool ok)
{
    if (!ok) return make_float4(0.f, 0.f, 0.f, 0.f);
    const float* src = (ch < 4)
        ? bankp   + (size_t)(pidx & 16383)*48 + ch*12
        : genh_in + (size_t)pidx*12;
    return *(const float4*)(src + q*4);
}

__device__ __forceinline__ float4 ldsrc_cls(const float* __restrict__ frame,
                                            const float* __restrict__ genh_new,
                                            const float* __restrict__ chh,
                                            int ch, int pidx, int q, bool ok)
{
    if (!ok) return make_float4(0.f, 0.f, 0.f, 0.f);
    const float* src = (ch == 0) ? frame + (size_t)(pidx & 4095)*12
                     : (ch == 1) ? genh_new + (size_t)pidx*12
                                 : chh + (size_t)pidx*12;
    return *(const float4*)(src + q*4);
}

// ==========================================================================
// General cell. grid (8,16)=(row-tile,batch), block 768 = 64 cols x 4
// rowgroups x 3 oc-thirds; each thread 2 rows x 16 oc -> local epilogue,
// single-float4 c/h traffic. 24 warps = 6/SMSP.
// ==========================================================================
#define A_SW   (9*60*48)            // 25920 floats
#define A_SIN  (12*660)             // 7920 floats, [icc][10 rows x 66 cols]
#define A_SMEM_BYTES ((A_SW + A_SIN + 48)*4)

__global__ __launch_bounds__(768, 1)
void gen_cell_kernel(const float* __restrict__ bias, int t, int par)
{
    extern __shared__ float smem[];
    float* sW  = smem;                 // [9][60][3][16]
    float* sIn = smem + A_SW;          // [12][660]
    float* sB  = smem + A_SW + A_SIN;  // [48] bias

    const int tid = threadIdx.x;
    const int tx  = tid & 63;
    const int rg  = (tid >> 6) & 3;
    const int th  = tid >> 8;          // 0..2
    const int b   = blockIdx.y;
    const int y0  = blockIdx.x * 8;
    const float* bankp = g_slabs[g_rslab[t*4 + (b >> 2)]];

    const float* genh_in  = g_genh[par];
    float*       genh_out = g_genh[par ^ 1];

    // Stage reordered weights: pure linear float4 copy
    {
        const float4* s4 = (const float4*)g_wg;
        float4*       d4 = (float4*)sW;
        #pragma unroll
        for (int i = 0; i < 9; ++i) {
            int e = tid + i*768;
            if (e < 6480) d4[e] = s4[e];
        }
    }
    if (tid < 12) ((float4*)sB)[tid] = ((const float4*)bias)[tid];

    // Precompute staging coordinates (3 slots/thread, invariant across ch)
    int ppx[3], pq[3], ppidx[3];
    bool pok[3], pinr[3];
    #pragma unroll
    for (int i = 0; i < 3; ++i) {
        int e  = tid + i*768;
        bool inr = e < 1980;
        int px = e/3, q = e - px*3;
        int yy = px/66, xx = px - yy*66;
        int gy = y0 + yy - 1, gx = xx - 1;
        bool inb = inr && (unsigned)gy < 64u && (unsigned)gx < 64u;
        ppx[i] = px; pq[i] = q;
        ppidx[i] = inb ? ((b*64 + gy)*64 + gx) : 0;
        pok[i] = inb; pinr[i] = inr;
    }

    ull acc0[8], acc1[8];
    #pragma unroll
    for (int p = 0; p < 8; ++p) { acc0[p] = 0ull; acc1[p] = 0ull; }

    float4 pf[3];
    #pragma unroll
    for (int i = 0; i < 3; ++i)
        pf[i] = ldsrc_gen(bankp, genh_in, 0, ppidx[i], pq[i], pok[i]);

    #pragma unroll 1
    for (int ch = 0; ch < 5; ++ch) {
        __syncthreads();
        #pragma unroll
        for (int i = 0; i < 3; ++i) {
            if (pinr[i]) {
                int base = pq[i]*4*660 + ppx[i];
                sIn[base]         = pf[i].x;
                sIn[base +  660]  = pf[i].y;
                sIn[base + 1320]  = pf[i].z;
                sIn[base + 1980]  = pf[i].w;
            }
        }
        __syncthreads();
        if (ch < 4) {
            #pragma unroll
            for (int i = 0; i < 3; ++i)
                pf[i] = ldsrc_gen(bankp, genh_in, ch + 1, ppidx[i], pq[i], pok[i]);
        }

        #pragma unroll 1
        for (int k = 0; k < 9; ++k) {
            const int ky = k / 3;
            const int kx = k - ky*3;
            conv12t(sW + ((k*60 + ch*12)*3 + th)*16,
                    sIn + (rg*2 + ky)*66 + tx + kx,
                    acc0, acc1);
        }
    }

    // Local LSTM epilogue: channels th*4..th*4+3 of all gates
    #pragma unroll
    for (int r = 0; r < 2; ++r) {
        ull* accr = r ? acc1 : acc0;
        float z[16];   // [i0..3 | f0..3 | g0..3 | o0..3]
        #pragma unroll
        for (int p = 0; p < 8; ++p) {
            float2 v = unpack2(accr[p]);
            z[2*p] = v.x; z[2*p+1] = v.y;
        }
        const int gy  = y0 + rg*2 + r;
        const int idx = ((b*64 + gy)*64 + tx)*12 + th*4;
        float4 c4 = *(const float4*)(g_genc + idx);
        float4 h4;
        float* cf = (float*)&c4;
        float* hf = (float*)&h4;
        #pragma unroll
        for (int j = 0; j < 4; ++j) {
            float zi = z[j]      + sB[th*4 + j];
            float zf = z[4 + j]  + sB[12 + th*4 + j];
            float zg = z[8 + j]  + sB[24 + th*4 + j];
            float zo = z[12 + j] + sB[36 + th*4 + j];
            float fi = hsig(zi), ff = hsig(zf), fo = hsig(zo);
            float cn = ff * cf[j] + fi * tanhf(zg);
            cf[j] = cn;
            hf[j] = fo * tanhf(cn);
        }
        *(float4*)(g_genc + idx)   = c4;
        *(float4*)(genh_out + idx) = h4;
    }
}

// ==========================================================================
// Class cell: 36 in-ch = 3 chunks of 12 (frame, fresh gen_h, class_h[cid]).
// Same 768-thread layout. Writes h_new into slab wslab[t]; accumulates out.
// ==========================================================================
#define B_SW   (9*36*48)            // 15552 floats
#define B_SIN  (12*660)
#define B_SMEM_BYTES ((B_SW + B_SIN + 48)*4)

__global__ __launch_bounds__(768, 1)
void cls_cell_kernel(const float* __restrict__ x, const int* __restrict__ class_ids,
                     const float* __restrict__ bias, int t, int par,
                     float* __restrict__ out)
{
    extern __shared__ float smem[];
    float* sW  = smem;                 // [9][36][3][16]
    float* sIn = smem + B_SW;
    float* sB  = smem + B_SW + B_SIN;

    const int tid = threadIdx.x;
    const int tx  = tid & 63;
    const int rg  = (tid >> 6) & 3;
    const int th  = tid >> 8;
    const int b   = blockIdx.y;
    const int y0  = blockIdx.x * 8;
    const int cid = __ldg(class_ids + t);

    const float* genh_new = g_genh[par ^ 1];
    const float* chh      = g_slabs[g_rslab[t*4 + cid]];
    float*       hnew     = g_slabs[g_wslab[t]];
    const float* frame    = x + (size_t)(b*NTT + t)*4096*12;

    {
        const float4* s4 = (const float4*)g_wc;
        float4*       d4 = (float4*)sW;
        #pragma unroll
        for (int i = 0; i < 6; ++i) {
            int e = tid + i*768;
            if (e < 3888) d4[e] = s4[e];
        }
    }
    if (tid < 12) ((float4*)sB)[tid] = ((const float4*)bias)[tid];

    int ppx[3], pq[3], ppidx[3];
    bool pok[3], pinr[3];
    #pragma unroll
    for (int i = 0; i < 3; ++i) {
        int e  = tid + i*768;
        bool inr = e < 1980;
        int px = e/3, q = e - px*3;
        int yy = px/66, xx = px - yy*66;
        int gy = y0 + yy - 1, gx = xx - 1;
        bool inb = inr && (unsigned)gy < 64u && (unsigned)gx < 64u;
        ppx[i] = px; pq[i] = q;
        ppidx[i] = inb ? ((b*64 + gy)*64 + gx) : 0;
        pok[i] = inb; pinr[i] = inr;
    }

    ull acc0[8], acc1[8];
    #pragma unroll
    for (int p = 0; p < 8; ++p) { acc0[p] = 0ull; acc1[p] = 0ull; }

    float4 pf[3];
    #pragma unroll
    for (int i = 0; i < 3; ++i)
        pf[i] = ldsrc_cls(frame, genh_new, chh, 0, ppidx[i], pq[i], pok[i]);

    #pragma unroll 1
    for (int ch = 0; ch < 3; ++ch) {
        __syncthreads();
        #pragma unroll
        for (int i = 0; i < 3; ++i) {
            if (pinr[i]) {
                int base = pq[i]*4*660 + ppx[i];
                sIn[base]         = pf[i].x;
                sIn[base +  660]  = pf[i].y;
                sIn[base + 1320]  = pf[i].z;
                sIn[base + 1980]  = pf[i].w;
            }
        }
        __syncthreads();
        if (ch < 2) {
            #pragma unroll
            for (int i = 0; i < 3; ++i)
                pf[i] = ldsrc_cls(frame, genh_new, chh, ch + 1, ppidx[i], pq[i], pok[i]);
        }

        #pragma unroll 1
        for (int k = 0; k < 9; ++k) {
            const int ky = k / 3;
            const int kx = k - ky*3;
            conv12t(sW + ((k*36 + ch*12)*3 + th)*16,
                    sIn + (rg*2 + ky)*66 + tx + kx,
                    acc0, acc1);
        }
    }

    float* chc = g_class_c + (size_t)cid * SSLICE;

    #pragma unroll
    for (int r = 0; r < 2; ++r) {
        ull* accr = r ? acc1 : acc0;
        float z[16];
        #pragma unroll
        for (int p = 0; p < 8; ++p) {
            float2 v = unpack2(accr[p]);
            z[2*p] = v.x; z[2*p+1] = v.y;
        }
        const int gy  = y0 + rg*2 + r;
        const int idx = ((b*64 + gy)*64 + tx)*12 + th*4;
        float4 c4 = *(const float4*)(chc + idx);
        float4 o4 = *(const float4*)(out + idx);
        float4 h4;
        float* cf = (float*)&c4;
        float* hf = (float*)&h4;
        float* of = (float*)&o4;
        #pragma unroll
        for (int j = 0; j < 4; ++j) {
            float zi = z[j]      + sB[th*4 + j];
            float zf = z[4 + j]  + sB[12 + th*4 + j];
            float zg = z[8 + j]  + sB[24 + th*4 + j];
            float zo = z[12 + j] + sB[36 + th*4 + j];
            float fi = hsig(zi), ff = hsig(zf), fo = hsig(zo);
            float cn = ff * cf[j] + fi * tanhf(zg);
            float hn = fo * tanhf(cn);
            cf[j] = cn;
            hf[j] = hn;
            of[j] += hn;
        }
        *(float4*)(chc + idx)  = c4;
        *(float4*)(hnew + idx) = h4;
        *(float4*)(out + idx)  = o4;
    }
}

// --------------------------------------------------------------------------
extern "C" void kernel_launch(void* const* d_in, const int* in_sizes, int n_in,
                              void* d_out, int out_size)
{
    const float* x    = (const float*)d_in[0];
    const int*   cids = (const int*)d_in[1];
    const float* Wxg  = (const float*)d_in[2];
    const float* Whg  = (const float*)d_in[3];
    const float* bg   = (const float*)d_in[4];
    const float* Wxc  = (const float*)d_in[5];
    const float* Whc  = (const float*)d_in[6];
    const float* bc   = (const float*)d_in[7];
    float* out = (float*)d_out;

    cudaFuncSetAttribute(gen_cell_kernel, cudaFuncAttributeMaxDynamicSharedMemorySize, A_SMEM_BYTES);
    cudaFuncSetAttribute(cls_cell_kernel, cudaFuncAttributeMaxDynamicSharedMemorySize, B_SMEM_BYTES);

    zero_kernel<<<1024, 256>>>(out, cids);
    reorder_kernel<<<64, 256>>>(Wxg, Whg, Wxc, Whc);

    for (int t = 0; t < NTT; ++t) {
        const int par = t & 1;
        gen_cell_kernel<<<dim3(8, 16), 768, A_SMEM_BYTES>>>(bg, t, par);
        cls_cell_kernel<<<dim3(8, 16), 768, B_SMEM_BYTES>>>(x, cids, bc, t, par, out);
    }
}